// round 1
// baseline (speedup 1.0000x reference)
#include <cuda_runtime.h>
#include <cuda_bf16.h>
#include <math.h>

// Problem constants (from reference): IN_F=2048, OUT_F=8192, NG=16, B=4096
#define K_DIM   2048
#define N_DIM   8192
#define NGROUPS 16
#define GSIZE   (N_DIM / NGROUPS)   // 512
#define EPS     1e-5f

#define TILE 128
#define KT   32
#define PAD  4   // smem row pad (keeps float4 alignment: 132 % 4 == 0)

// ---------------------------------------------------------------------------
// GEMM: C[m][n] = sum_k x[m][k] * W[n][k] + b[n]
// A = x [M,K] row-major, B = W [N,K] row-major (so C = A * B^T)
// 128x128 block tile, 256 threads, 8x8 per-thread microtile, K-tile = 32.
// ---------------------------------------------------------------------------
__global__ __launch_bounds__(256, 2)
void gemm_bias_kernel(const float* __restrict__ A,
                      const float* __restrict__ Bm,
                      const float* __restrict__ bias,
                      float* __restrict__ C,
                      int M, int N, int K)
{
    __shared__ float As[KT][TILE + PAD];
    __shared__ float Bs[KT][TILE + PAD];

    const int tid = threadIdx.x;          // 0..255
    const int tx  = tid & 15;             // 0..15 -> column microtile
    const int ty  = tid >> 4;             // 0..15 -> row microtile

    const int bx = blockIdx.x;            // N tile
    const int by = blockIdx.y;            // M tile

    const float* Aptr = A  + (size_t)(by * TILE) * K;
    const float* Bptr = Bm + (size_t)(bx * TILE) * K;

    float acc[8][8];
#pragma unroll
    for (int i = 0; i < 8; i++)
#pragma unroll
        for (int j = 0; j < 8; j++) acc[i][j] = 0.0f;

    for (int k0 = 0; k0 < K; k0 += KT) {
        // ---- Stage tiles into shared memory (transposed: [k][row]) ----
        // 128 rows x 32 floats = 1024 float4; 256 threads -> 4 float4 each per matrix.
#pragma unroll
        for (int i = 0; i < 4; i++) {
            int idx = tid + i * 256;      // 0..1023
            int row = idx >> 3;           // 0..127
            int c4  = idx & 7;            // float4 slot within 32-float row
            float4 va = *reinterpret_cast<const float4*>(Aptr + (size_t)row * K + k0 + c4 * 4);
            As[c4 * 4 + 0][row] = va.x;
            As[c4 * 4 + 1][row] = va.y;
            As[c4 * 4 + 2][row] = va.z;
            As[c4 * 4 + 3][row] = va.w;
            float4 vb = *reinterpret_cast<const float4*>(Bptr + (size_t)row * K + k0 + c4 * 4);
            Bs[c4 * 4 + 0][row] = vb.x;
            Bs[c4 * 4 + 1][row] = vb.y;
            Bs[c4 * 4 + 2][row] = vb.z;
            Bs[c4 * 4 + 3][row] = vb.w;
        }
        __syncthreads();

        // ---- Compute ----
#pragma unroll
        for (int k = 0; k < KT; k++) {
            float a[8], bb[8];
#pragma unroll
            for (int i = 0; i < 8; i++) a[i]  = As[k][ty * 8 + i];
#pragma unroll
            for (int j = 0; j < 8; j++) bb[j] = Bs[k][tx * 8 + j];
#pragma unroll
            for (int i = 0; i < 8; i++)
#pragma unroll
                for (int j = 0; j < 8; j++)
                    acc[i][j] = fmaf(a[i], bb[j], acc[i][j]);
        }
        __syncthreads();
    }

    // ---- Epilogue: add bias, store ----
    const int row0 = by * TILE + ty * 8;
    const int col0 = bx * TILE + tx * 8;
    float bj[8];
#pragma unroll
    for (int j = 0; j < 8; j++) bj[j] = bias[col0 + j];

#pragma unroll
    for (int i = 0; i < 8; i++) {
        float4 o0, o1;
        o0.x = acc[i][0] + bj[0];
        o0.y = acc[i][1] + bj[1];
        o0.z = acc[i][2] + bj[2];
        o0.w = acc[i][3] + bj[3];
        o1.x = acc[i][4] + bj[4];
        o1.y = acc[i][5] + bj[5];
        o1.z = acc[i][6] + bj[6];
        o1.w = acc[i][7] + bj[7];
        float* crow = C + (size_t)(row0 + i) * N + col0;
        *reinterpret_cast<float4*>(crow)     = o0;
        *reinterpret_cast<float4*>(crow + 4) = o1;
    }
}

// ---------------------------------------------------------------------------
// GroupNorm + SiLU + mult_w + SiLU, in place on y (= d_out).
// One block per (row, group). Group = 512 contiguous channels.
// 128 threads, 4 elements (one float4) each.
// ---------------------------------------------------------------------------
__device__ __forceinline__ float sigmoidf_(float x) {
    return 1.0f / (1.0f + expf(-x));
}

__global__ __launch_bounds__(128)
void gn_silu_kernel(float* __restrict__ y,
                    const float* __restrict__ gn_w,
                    const float* __restrict__ gn_b,
                    const float* __restrict__ mult_w,
                    int N)
{
    const int row = blockIdx.x;
    const int g   = blockIdx.y;
    const int tid = threadIdx.x;      // 0..127

    float* p = y + (size_t)row * N + g * GSIZE;

    float4 v = reinterpret_cast<const float4*>(p)[tid];

    float s  = v.x + v.y + v.z + v.w;
    float ss = v.x * v.x + v.y * v.y + v.z * v.z + v.w * v.w;

    // warp reduce
#pragma unroll
    for (int o = 16; o > 0; o >>= 1) {
        s  += __shfl_down_sync(0xffffffffu, s,  o);
        ss += __shfl_down_sync(0xffffffffu, ss, o);
    }
    __shared__ float ws[4], wss[4];
    const int warp = tid >> 5;
    const int lane = tid & 31;
    if (lane == 0) { ws[warp] = s; wss[warp] = ss; }
    __syncthreads();
    s  = ws[0]  + ws[1]  + ws[2]  + ws[3];
    ss = wss[0] + wss[1] + wss[2] + wss[3];

    const float inv_n = 1.0f / (float)GSIZE;
    const float mean  = s * inv_n;
    const float var   = fmaxf(ss * inv_n - mean * mean, 0.0f);
    const float rstd  = rsqrtf(var + EPS);

    const int c0 = g * GSIZE + tid * 4;
    float vals[4] = {v.x, v.y, v.z, v.w};
    float out[4];
#pragma unroll
    for (int i = 0; i < 4; i++) {
        int c = c0 + i;
        float n  = (vals[i] - mean) * rstd * gn_w[c] + gn_b[c];
        float s1 = n * sigmoidf_(n);
        float m  = s1 * mult_w[c];
        out[i]   = m * sigmoidf_(m);
    }
    float4 o = {out[0], out[1], out[2], out[3]};
    reinterpret_cast<float4*>(p)[tid] = o;
}

// ---------------------------------------------------------------------------
extern "C" void kernel_launch(void* const* d_in, const int* in_sizes, int n_in,
                              void* d_out, int out_size)
{
    const float* x      = (const float*)d_in[0];
    const float* W      = (const float*)d_in[1];
    const float* b      = (const float*)d_in[2];
    const float* gn_w   = (const float*)d_in[3];
    const float* gn_b   = (const float*)d_in[4];
    const float* mult_w = (const float*)d_in[5];
    float* out = (float*)d_out;

    const int K = K_DIM;
    const int N = N_DIM;
    const int M = in_sizes[0] / K;   // 4096

    dim3 ggrid(N / TILE, M / TILE);  // (64, 32)
    gemm_bias_kernel<<<ggrid, 256>>>(x, W, b, out, M, N, K);

    dim3 ngrid(M, NGROUPS);          // (4096, 16)
    gn_silu_kernel<<<ngrid, 128>>>(out, gn_w, gn_b, mult_w, N);
}

// round 3
// speedup vs baseline: 2.9867x; 2.9867x over previous
#include <cuda_runtime.h>
#include <cuda_bf16.h>
#include <cstdint>
#include <math.h>

// Problem constants: B=4096, IN_F=2048, OUT_F=8192, NG=16
#define M_DIM   4096
#define K_DIM   2048
#define N_DIM   8192
#define NGROUPS 16
#define GSIZE   (N_DIM / NGROUPS)   // 512
#define EPS     1e-5f

// GEMM tiling
#define BM 128
#define BN 128
#define CHUNK 64                    // K elements per stage (128 B rows of bf16)
#define NCHUNK (K_DIM / CHUNK)      // 32

// SMEM: per stage [Ah 16K][Al 16K][Bh 16K][Bl 16K] = 64 KB, 2 stages
#define OFF_AH 0
#define OFF_AL 16384
#define OFF_BH 32768
#define OFF_BL 49152
#define STAGE_BYTES 65536
#define SMEM_TOTAL (2 * STAGE_BYTES)    // 131072

#define SWZ(o) ((o) ^ ((((uint32_t)(o)) >> 3) & 0x70))

// -------- scratch: bf16 hi/lo splits ----------------------------------------
__device__ __nv_bfloat16 g_xh[(size_t)M_DIM * K_DIM];
__device__ __nv_bfloat16 g_xl[(size_t)M_DIM * K_DIM];
__device__ __nv_bfloat16 g_wh[(size_t)N_DIM * K_DIM];
__device__ __nv_bfloat16 g_wl[(size_t)N_DIM * K_DIM];

// -------- PTX helpers (all plain sm_80+ — no 'a' features) ------------------
__device__ __forceinline__ uint32_t smem_u32(const void* p) {
    uint32_t a;
    asm("{ .reg .u64 t; cvta.to.shared.u64 t, %1; cvt.u32.u64 %0, t; }" : "=r"(a) : "l"(p));
    return a;
}
#define CP_ASYNC16(dst, src) \
    asm volatile("cp.async.cg.shared.global [%0], [%1], 16;" :: "r"(dst), "l"(src) : "memory")
#define CP_COMMIT() asm volatile("cp.async.commit_group;" ::: "memory")
#define CP_WAIT(n)  asm volatile("cp.async.wait_group %0;" :: "n"(n) : "memory")

#define LDSM_X4(r0, r1, r2, r3, addr) \
    asm volatile("ldmatrix.sync.aligned.m8n8.x4.shared.b16 {%0,%1,%2,%3}, [%4];" \
        : "=r"(r0), "=r"(r1), "=r"(r2), "=r"(r3) : "r"(addr))

#define MMA16816(d, a, b0v, b1v) \
    asm volatile("mma.sync.aligned.m16n8k16.row.col.f32.bf16.bf16.f32 " \
        "{%0,%1,%2,%3}, {%4,%5,%6,%7}, {%8,%9}, {%0,%1,%2,%3};" \
        : "+f"((d)[0]), "+f"((d)[1]), "+f"((d)[2]), "+f"((d)[3]) \
        : "r"((a)[0]), "r"((a)[1]), "r"((a)[2]), "r"((a)[3]), "r"(b0v), "r"(b1v))

// -------- split fp32 -> bf16 hi/lo ------------------------------------------
__global__ __launch_bounds__(256)
void split_kernel(const float* __restrict__ src,
                  __nv_bfloat16* __restrict__ hi,
                  __nv_bfloat16* __restrict__ lo, int n4)
{
    int i = blockIdx.x * 256 + threadIdx.x;
    if (i >= n4) return;
    float4 v = reinterpret_cast<const float4*>(src)[i];
    __nv_bfloat16 h0 = __float2bfloat16(v.x), h1 = __float2bfloat16(v.y);
    __nv_bfloat16 h2 = __float2bfloat16(v.z), h3 = __float2bfloat16(v.w);
    __nv_bfloat16 l0 = __float2bfloat16(v.x - __bfloat162float(h0));
    __nv_bfloat16 l1 = __float2bfloat16(v.y - __bfloat162float(h1));
    __nv_bfloat16 l2 = __float2bfloat16(v.z - __bfloat162float(h2));
    __nv_bfloat16 l3 = __float2bfloat16(v.w - __bfloat162float(h3));
    uint2 uh, ul;
    uh.x = (uint32_t)__bfloat16_as_ushort(h0) | ((uint32_t)__bfloat16_as_ushort(h1) << 16);
    uh.y = (uint32_t)__bfloat16_as_ushort(h2) | ((uint32_t)__bfloat16_as_ushort(h3) << 16);
    ul.x = (uint32_t)__bfloat16_as_ushort(l0) | ((uint32_t)__bfloat16_as_ushort(l1) << 16);
    ul.y = (uint32_t)__bfloat16_as_ushort(l2) | ((uint32_t)__bfloat16_as_ushort(l3) << 16);
    reinterpret_cast<uint2*>(hi)[i] = uh;
    reinterpret_cast<uint2*>(lo)[i] = ul;
}

// -------- HMMA GEMM: C = x @ W^T + b  (bf16x3 split) ------------------------
__global__ __launch_bounds__(256, 1)
void gemm_hmma_kernel(const float* __restrict__ bias, float* __restrict__ C)
{
    extern __shared__ __align__(128) char sm[];
    const uint32_t smem_base = smem_u32(sm);

    const int tid  = threadIdx.x;
    const int wid  = tid >> 5;
    const int lane = tid & 31;
    const int wm   = wid & 3;       // 0..3  -> 32 M rows each
    const int wn   = wid >> 2;      // 0..1  -> 64 N cols each

    const int mrow0 = blockIdx.x * BM;   // grid.x = M tiles (32)
    const int nrow0 = blockIdx.y * BN;   // grid.y = N tiles (64)

    float acc[2][8][4];
#pragma unroll
    for (int i = 0; i < 2; i++)
#pragma unroll
        for (int j = 0; j < 8; j++)
#pragma unroll
            for (int r = 0; r < 4; r++) acc[i][j][r] = 0.0f;

    // ---- async prefetch of one chunk into stage s ----
    auto prefetch = [&](int c) {
        const int s = c & 1;
        const int k0 = c * CHUNK;
        const uint32_t base = smem_base + s * STAGE_BYTES;
#pragma unroll
        for (int i = 0; i < 4; i++) {
            int idx = tid + i * 256;             // 0..1023
            int r = idx >> 3, u = idx & 7;       // row, 16B chunk
            uint32_t sw = SWZ(r * 128 + u * 16);
            size_t ga = (size_t)(mrow0 + r) * K_DIM + k0 + u * 8;
            size_t gb = (size_t)(nrow0 + r) * K_DIM + k0 + u * 8;
            CP_ASYNC16(base + OFF_AH + sw, &g_xh[ga]);
            CP_ASYNC16(base + OFF_AL + sw, &g_xl[ga]);
            CP_ASYNC16(base + OFF_BH + sw, &g_wh[gb]);
            CP_ASYNC16(base + OFF_BL + sw, &g_wl[gb]);
        }
    };

    prefetch(0);
    CP_COMMIT();

    for (int c = 0; c < NCHUNK; ++c) {
        if (c + 1 < NCHUNK) prefetch(c + 1);
        CP_COMMIT();
        CP_WAIT(1);                  // stage c ready
        __syncthreads();

        const uint32_t base = smem_base + (c & 1) * STAGE_BYTES;

        // per-lane ldmatrix address components
        const int a_row = wm * 32 + (lane & 15);          // + i*16
        const int a_kb  = (lane >> 4) * 16;               // + ks*32
        const int b_row = wn * 64 + (lane & 7) + ((lane >> 4) << 3);  // + j*16
        const int b_kb  = ((lane >> 3) & 1) * 16;         // + ks*32

#pragma unroll
        for (int ks = 0; ks < 4; ++ks) {
            uint32_t ah[2][4], al[2][4], bh[4][4], bl[4][4];

            // load Ah (2 m-tiles), Bh (4 x4 = 8 n-tiles)
#pragma unroll
            for (int i = 0; i < 2; i++) {
                uint32_t ad = base + OFF_AH + SWZ((a_row + i * 16) * 128 + ks * 32 + a_kb);
                LDSM_X4(ah[i][0], ah[i][1], ah[i][2], ah[i][3], ad);
            }
#pragma unroll
            for (int j = 0; j < 4; j++) {
                uint32_t bd = base + OFF_BH + SWZ((b_row + j * 16) * 128 + ks * 32 + b_kb);
                LDSM_X4(bh[j][0], bh[j][1], bh[j][2], bh[j][3], bd);
            }
            // pass 1: Ah * Bh
#pragma unroll
            for (int i = 0; i < 2; i++)
#pragma unroll
                for (int j = 0; j < 4; j++) {
                    MMA16816(acc[i][2 * j + 0], ah[i], bh[j][0], bh[j][1]);
                    MMA16816(acc[i][2 * j + 1], ah[i], bh[j][2], bh[j][3]);
                }
            // pass 2: Al * Bh
#pragma unroll
            for (int i = 0; i < 2; i++) {
                uint32_t ad = base + OFF_AL + SWZ((a_row + i * 16) * 128 + ks * 32 + a_kb);
                LDSM_X4(al[i][0], al[i][1], al[i][2], al[i][3], ad);
            }
#pragma unroll
            for (int i = 0; i < 2; i++)
#pragma unroll
                for (int j = 0; j < 4; j++) {
                    MMA16816(acc[i][2 * j + 0], al[i], bh[j][0], bh[j][1]);
                    MMA16816(acc[i][2 * j + 1], al[i], bh[j][2], bh[j][3]);
                }
            // pass 3: Ah * Bl
#pragma unroll
            for (int j = 0; j < 4; j++) {
                uint32_t bd = base + OFF_BL + SWZ((b_row + j * 16) * 128 + ks * 32 + b_kb);
                LDSM_X4(bl[j][0], bl[j][1], bl[j][2], bl[j][3], bd);
            }
#pragma unroll
            for (int i = 0; i < 2; i++)
#pragma unroll
                for (int j = 0; j < 4; j++) {
                    MMA16816(acc[i][2 * j + 0], ah[i], bl[j][0], bl[j][1]);
                    MMA16816(acc[i][2 * j + 1], ah[i], bl[j][2], bl[j][3]);
                }
        }
        __syncthreads();
    }

    // ---- epilogue: + bias, store fp32 ----
    const int m_base = mrow0 + wm * 32 + (lane >> 2);
    const int n_base = nrow0 + wn * 64 + (lane & 3) * 2;
#pragma unroll
    for (int i = 0; i < 2; i++) {
#pragma unroll
        for (int j = 0; j < 8; j++) {
            int n0 = n_base + j * 8;
            float b0 = bias[n0], b1 = bias[n0 + 1];
            int m0 = m_base + i * 16;
            float2 lo2 = {acc[i][j][0] + b0, acc[i][j][1] + b1};
            float2 hi2 = {acc[i][j][2] + b0, acc[i][j][3] + b1};
            *reinterpret_cast<float2*>(C + (size_t)m0 * N_DIM + n0)       = lo2;
            *reinterpret_cast<float2*>(C + (size_t)(m0 + 8) * N_DIM + n0) = hi2;
        }
    }
}

// -------- GroupNorm + SiLU + mult + SiLU (in place) -------------------------
__device__ __forceinline__ float sigmoidf_(float x) { return 1.0f / (1.0f + expf(-x)); }

__global__ __launch_bounds__(128)
void gn_silu_kernel(float* __restrict__ y,
                    const float* __restrict__ gn_w,
                    const float* __restrict__ gn_b,
                    const float* __restrict__ mult_w, int N)
{
    const int row = blockIdx.x;
    const int g   = blockIdx.y;
    const int tid = threadIdx.x;

    float* p = y + (size_t)row * N + g * GSIZE;
    float4 v = reinterpret_cast<const float4*>(p)[tid];

    float s  = v.x + v.y + v.z + v.w;
    float ss = v.x*v.x + v.y*v.y + v.z*v.z + v.w*v.w;
#pragma unroll
    for (int o = 16; o > 0; o >>= 1) {
        s  += __shfl_down_sync(0xffffffffu, s,  o);
        ss += __shfl_down_sync(0xffffffffu, ss, o);
    }
    __shared__ float ws[4], wss[4];
    const int warp = tid >> 5, lane = tid & 31;
    if (lane == 0) { ws[warp] = s; wss[warp] = ss; }
    __syncthreads();
    s  = ws[0] + ws[1] + ws[2] + ws[3];
    ss = wss[0] + wss[1] + wss[2] + wss[3];

    const float inv_n = 1.0f / (float)GSIZE;
    const float mean  = s * inv_n;
    const float var   = fmaxf(ss * inv_n - mean * mean, 0.0f);
    const float rstd  = rsqrtf(var + EPS);

    const int c0 = g * GSIZE + tid * 4;
    float vals[4] = {v.x, v.y, v.z, v.w};
    float out[4];
#pragma unroll
    for (int i = 0; i < 4; i++) {
        int c = c0 + i;
        float n  = (vals[i] - mean) * rstd * gn_w[c] + gn_b[c];
        float s1 = n * sigmoidf_(n);
        float m  = s1 * mult_w[c];
        out[i]   = m * sigmoidf_(m);
    }
    float4 o = {out[0], out[1], out[2], out[3]};
    reinterpret_cast<float4*>(p)[tid] = o;
}

// ---------------------------------------------------------------------------
extern "C" void kernel_launch(void* const* d_in, const int* in_sizes, int n_in,
                              void* d_out, int out_size)
{
    const float* x      = (const float*)d_in[0];
    const float* W      = (const float*)d_in[1];
    const float* b      = (const float*)d_in[2];
    const float* gn_w   = (const float*)d_in[3];
    const float* gn_b   = (const float*)d_in[4];
    const float* mult_w = (const float*)d_in[5];
    float* out = (float*)d_out;

    __nv_bfloat16 *xh, *xl, *wh, *wl;
    cudaGetSymbolAddress((void**)&xh, g_xh);
    cudaGetSymbolAddress((void**)&xl, g_xl);
    cudaGetSymbolAddress((void**)&wh, g_wh);
    cudaGetSymbolAddress((void**)&wl, g_wl);

    int n4x = (M_DIM * K_DIM) / 4;
    int n4w = (N_DIM * K_DIM) / 4;
    split_kernel<<<(n4x + 255) / 256, 256>>>(x, xh, xl, n4x);
    split_kernel<<<(n4w + 255) / 256, 256>>>(W, wh, wl, n4w);

    cudaFuncSetAttribute(gemm_hmma_kernel,
                         cudaFuncAttributeMaxDynamicSharedMemorySize, SMEM_TOTAL);

    dim3 ggrid(M_DIM / BM, N_DIM / BN);   // (32, 64): M fast for B-reuse in L2
    gemm_hmma_kernel<<<ggrid, 256, SMEM_TOTAL>>>(b, out);

    dim3 ngrid(M_DIM, NGROUPS);
    gn_silu_kernel<<<ngrid, 128>>>(out, gn_w, gn_b, mult_w, N_DIM);
}